// round 9
// baseline (speedup 1.0000x reference)
#include <cuda_runtime.h>
#include <cuda_fp16.h>
#include <stdint.h>

#define NN 50000
#define EE 800000
#define C  128
#define SCAN_BLOCKS ((NN + 1023) / 1024)   // 49
#define GEMM_GRID   ((NN + 127) / 128)     // 391
#define FILL_GRID   ((EE / 4 + 255) / 256) // 782
#define AGG_GRID    ((NN + 7) / 8)         // 6250

// ---------------- scratch (device globals; no allocation) ----------------
// NOTE: g_deg and g_stat are zero on entry to every call: they are
// zero-initialized at load, and k_agg2_head (last kernel of every call)
// re-zeroes them for the next call. Deterministic across replays.
__device__ __half g_hp[(size_t)NN * C];   // h' (dinv-scaled gemm out, fp16)
__device__ __half g_h1[(size_t)NN * C];   // h1 (post agg/relu, fp16)
__device__ int    g_deg[NN];
__device__ float  g_dinv[NN];
__device__ int    g_rowptr[NN + 1];
__device__ int    g_cnt[NN];
__device__ int    g_srcs[EE];
__device__ unsigned long long g_stat[SCAN_BLOCKS];  // (value<<2)|flag

// ---------------- vector load helpers ----------------
__device__ __forceinline__ float4 ld4v(const float* X, size_t off4) {
    return ((const float4*)X)[off4];
}
__device__ __forceinline__ float4 ld4v(const __half* X, size_t off4) {
    uint2 u = ((const uint2*)X)[off4];
    __half2 a = *(__half2*)&u.x, b = *(__half2*)&u.y;
    float2 fa = __half22float2(a), fb = __half22float2(b);
    return make_float4(fa.x, fa.y, fb.x, fb.y);
}
__device__ __forceinline__ void st4h(__half* out, size_t off4, float4 v) {
    uint2 u;
    __half2 lo = __floats2half2_rn(v.x, v.y);
    __half2 hi = __floats2half2_rn(v.z, v.w);
    u.x = *(unsigned*)&lo; u.y = *(unsigned*)&hi;
    ((uint2*)out)[off4] = u;
}

// ---------------- CSR: count ----------------
__global__ void k_count_deg(const int* __restrict__ ei) {
    int e4 = blockIdx.x * blockDim.x + threadIdx.x;
    if (e4 < EE / 4) {
        int4 d = ((const int4*)(ei + EE))[e4];
        atomicAdd(&g_deg[d.x], 1);
        atomicAdd(&g_deg[d.y], 1);
        atomicAdd(&g_deg[d.z], 1);
        atomicAdd(&g_deg[d.w], 1);
    }
}

// ---------------- CSR: single-pass scan (decoupled lookback) -------------
// 49 blocks x 1024 thr (all co-resident on 148 SMs -> lookback cannot hang).
// Produces dinv, rowptr, cnt, rowptr[NN].
__global__ void k_scan1() {
    __shared__ int wsum[32];
    __shared__ int s_off;
    int tid = threadIdx.x;
    int lane = tid & 31, wid = tid >> 5;
    int bid = blockIdx.x;
    int i = bid * 1024 + tid;
    int v = (i < NN) ? g_deg[i] : 0;

    if (i < NN) g_dinv[i] = rsqrtf((float)v + 1.0f);

    int s = v;
    #pragma unroll
    for (int off = 1; off < 32; off <<= 1) {
        int t = __shfl_up_sync(0xffffffffu, s, off);
        if (lane >= off) s += t;
    }
    if (lane == 31) wsum[wid] = s;
    __syncthreads();
    if (wid == 0) {
        int ws = wsum[lane];
        #pragma unroll
        for (int off = 1; off < 32; off <<= 1) {
            int t = __shfl_up_sync(0xffffffffu, ws, off);
            if (lane >= off) ws += t;
        }
        wsum[lane] = ws;  // inclusive over warp sums
    }
    __syncthreads();

    int excl = s - v + (wid > 0 ? wsum[wid - 1] : 0);
    int T = wsum[31];  // block total

    if (tid == 0) {
        if (bid == 0) {
            atomicExch(&g_stat[0], ((unsigned long long)T << 2) | 2ull);
            s_off = 0;
        } else {
            // publish partial
            atomicExch(&g_stat[bid], ((unsigned long long)T << 2) | 1ull);
            // lookback
            int sum = 0;
            int p = bid - 1;
            while (true) {
                unsigned long long st;
                do { st = atomicAdd(&g_stat[p], 0ull); } while ((st & 3ull) == 0ull);
                sum += (int)(st >> 2);
                if ((st & 3ull) == 2ull) break;
                p--;
            }
            // publish inclusive
            atomicExch(&g_stat[bid], ((unsigned long long)(sum + T) << 2) | 2ull);
            s_off = sum;
        }
    }
    __syncthreads();

    int off = s_off;
    if (i < NN) {
        int rp = excl + off;
        g_rowptr[i] = rp;
        g_cnt[i]    = rp;
    }
    if (bid == SCAN_BLOCKS - 1 && tid == 0)
        g_rowptr[NN] = off + T;
}

// ---------------- FP16 tensor-core GEMM (m16n8k16) -----------------------
__device__ __forceinline__ void mma_fp16(float* c, unsigned a0, unsigned a1,
                                         unsigned a2, unsigned a3,
                                         unsigned b0, unsigned b1) {
    asm volatile(
        "mma.sync.aligned.m16n8k16.row.col.f32.f16.f16.f32 "
        "{%0,%1,%2,%3}, {%4,%5,%6,%7}, {%8,%9}, {%0,%1,%2,%3};"
        : "+f"(c[0]), "+f"(c[1]), "+f"(c[2]), "+f"(c[3])
        : "r"(a0), "r"(a1), "r"(a2), "r"(a3), "r"(b0), "r"(b1));
}

#define KS 72

template <typename Tin>
__device__ __forceinline__ void gemm128_body(const Tin* __restrict__ X,
                                             const float* __restrict__ W,
                                             __half* __restrict__ out,
                                             int n, int bx) {
    __shared__ __half Xs[128 * KS];
    __shared__ __half Wt[128 * KS];

    int tid = threadIdx.x;
    int warp = tid >> 5, lane = tid & 31;
    int warp_m = warp >> 2, warp_n = warp & 3;
    int row0 = bx * 128;
    int lq = lane & 3, lg = lane >> 2;

    float acc[4][4][4];
    #pragma unroll
    for (int mt = 0; mt < 4; mt++)
        #pragma unroll
        for (int nt = 0; nt < 4; nt++)
            #pragma unroll
            for (int k = 0; k < 4; k++) acc[mt][nt][k] = 0.f;

    #pragma unroll
    for (int kc = 0; kc < 2; kc++) {
        #pragma unroll
        for (int i = 0; i < 8; i++) {
            int idx = tid + 256 * i;
            int r = idx >> 4, kq = idx & 15;
            float4 v = make_float4(0.f, 0.f, 0.f, 0.f);
            if (row0 + r < n)
                v = ld4v(X, (size_t)(row0 + r) * 32 + kc * 16 + kq);
            __half2* p = (__half2*)&Xs[r * KS + kq * 4];
            p[0] = __floats2half2_rn(v.x, v.y);
            p[1] = __floats2half2_rn(v.z, v.w);
        }
        #pragma unroll
        for (int i = 0; i < 4; i++) {
            int idx = tid + 256 * i;
            int kp = idx & 31, n4 = idx >> 5;
            int k0 = kc * 64 + kp * 2;
            float4 a = ((const float4*)W)[(size_t)k0 * 32 + n4];
            float4 b = ((const float4*)W)[(size_t)(k0 + 1) * 32 + n4];
            int nb = n4 * 4;
            *(__half2*)&Wt[(nb + 0) * KS + kp * 2] = __floats2half2_rn(a.x, b.x);
            *(__half2*)&Wt[(nb + 1) * KS + kp * 2] = __floats2half2_rn(a.y, b.y);
            *(__half2*)&Wt[(nb + 2) * KS + kp * 2] = __floats2half2_rn(a.z, b.z);
            *(__half2*)&Wt[(nb + 3) * KS + kp * 2] = __floats2half2_rn(a.w, b.w);
        }
        __syncthreads();

        #pragma unroll
        for (int ks = 0; ks < 4; ks++) {
            int kb = ks * 16;
            unsigned b[4][2];
            #pragma unroll
            for (int nt = 0; nt < 4; nt++) {
                int nn = warp_n * 32 + nt * 8 + lg;
                b[nt][0] = *(unsigned*)&Wt[nn * KS + kb + 2 * lq];
                b[nt][1] = *(unsigned*)&Wt[nn * KS + kb + 8 + 2 * lq];
            }
            #pragma unroll
            for (int mt = 0; mt < 4; mt++) {
                int mm = warp_m * 64 + mt * 16 + lg;
                unsigned a0 = *(unsigned*)&Xs[mm * KS + kb + 2 * lq];
                unsigned a1 = *(unsigned*)&Xs[(mm + 8) * KS + kb + 2 * lq];
                unsigned a2 = *(unsigned*)&Xs[mm * KS + kb + 8 + 2 * lq];
                unsigned a3 = *(unsigned*)&Xs[(mm + 8) * KS + kb + 8 + 2 * lq];
                #pragma unroll
                for (int nt = 0; nt < 4; nt++)
                    mma_fp16(acc[mt][nt], a0, a1, a2, a3, b[nt][0], b[nt][1]);
            }
        }
        __syncthreads();
    }

    #pragma unroll
    for (int mt = 0; mt < 4; mt++) {
        int r = row0 + warp_m * 64 + mt * 16 + lg;
        float s0 = (r < n)     ? g_dinv[r]     : 0.f;
        float s1 = (r + 8 < n) ? g_dinv[r + 8] : 0.f;
        #pragma unroll
        for (int nt = 0; nt < 4; nt++) {
            int cc = warp_n * 32 + nt * 8 + lq * 2;
            if (r < n) {
                __half2 h = __floats2half2_rn(acc[mt][nt][0] * s0, acc[mt][nt][1] * s0);
                *(__half2*)&out[(size_t)r * C + cc] = h;
            }
            if (r + 8 < n) {
                __half2 h = __floats2half2_rn(acc[mt][nt][2] * s1, acc[mt][nt][3] * s1);
                *(__half2*)&out[(size_t)(r + 8) * C + cc] = h;
            }
        }
    }
}

// ---------------- fat kernel: GEMM layer1 + fill_csr ----------------
__global__ void k_gemm1_fill(const float* __restrict__ X,
                             const float* __restrict__ W,
                             const int* __restrict__ ei) {
    if (blockIdx.x < GEMM_GRID) {
        gemm128_body(X, W, g_hp, NN, blockIdx.x);
    } else {
        int e4 = (blockIdx.x - GEMM_GRID) * blockDim.x + threadIdx.x;
        if (e4 < EE / 4) {
            int4 s = ((const int4*)ei)[e4];
            int4 d = ((const int4*)(ei + EE))[e4];
            g_srcs[atomicAdd(&g_cnt[d.x], 1)] = s.x;
            g_srcs[atomicAdd(&g_cnt[d.y], 1)] = s.y;
            g_srcs[atomicAdd(&g_cnt[d.z], 1)] = s.z;
            g_srcs[atomicAdd(&g_cnt[d.w], 1)] = s.w;
        }
    }
}

// ---------------- aggregation over pre-normalized fp16 h' -----------------
__device__ __forceinline__ float4 agg_row(const __half* __restrict__ hp,
                                          const float4* __restrict__ b4,
                                          int node, int lane) {
    float di = g_dinv[node];
    int e = g_rowptr[node], end = g_rowptr[node + 1];

    float4 a0 = make_float4(0.f, 0.f, 0.f, 0.f);
    float4 a1 = make_float4(0.f, 0.f, 0.f, 0.f);
    float4 a2 = make_float4(0.f, 0.f, 0.f, 0.f);
    float4 a3 = make_float4(0.f, 0.f, 0.f, 0.f);
    for (; e + 3 < end; e += 4) {
        int s0 = g_srcs[e],     s1 = g_srcs[e + 1];
        int s2 = g_srcs[e + 2], s3 = g_srcs[e + 3];
        float4 v0 = ld4v(hp, (size_t)s0 * 32 + lane);
        float4 v1 = ld4v(hp, (size_t)s1 * 32 + lane);
        float4 v2 = ld4v(hp, (size_t)s2 * 32 + lane);
        float4 v3 = ld4v(hp, (size_t)s3 * 32 + lane);
        a0.x += v0.x; a0.y += v0.y; a0.z += v0.z; a0.w += v0.w;
        a1.x += v1.x; a1.y += v1.y; a1.z += v1.z; a1.w += v1.w;
        a2.x += v2.x; a2.y += v2.y; a2.z += v2.z; a2.w += v2.w;
        a3.x += v3.x; a3.y += v3.y; a3.z += v3.z; a3.w += v3.w;
    }
    for (; e < end; e++) {
        float4 v = ld4v(hp, (size_t)g_srcs[e] * 32 + lane);
        a0.x += v.x; a0.y += v.y; a0.z += v.z; a0.w += v.w;
    }
    float4 sv = ld4v(hp, (size_t)node * 32 + lane);  // self
    a0.x += a1.x + a2.x + a3.x + sv.x;
    a0.y += a1.y + a2.y + a3.y + sv.y;
    a0.z += a1.z + a2.z + a3.z + sv.z;
    a0.w += a1.w + a2.w + a3.w + sv.w;

    float4 b = b4[lane];
    float4 o;
    o.x = fmaxf(fmaf(di, a0.x, b.x), 0.f);
    o.y = fmaxf(fmaf(di, a0.y, b.y), 0.f);
    o.z = fmaxf(fmaf(di, a0.z, b.z), 0.f);
    o.w = fmaxf(fmaf(di, a0.w, b.w), 0.f);
    return o;
}

__global__ void k_agg_l1(const float* __restrict__ bias) {
    int node = blockIdx.x * (blockDim.x >> 5) + (threadIdx.x >> 5);
    if (node >= NN) return;
    int lane = threadIdx.x & 31;
    float4 o = agg_row(g_hp, (const float4*)bias, node, lane);
    st4h(g_h1, (size_t)node * 32 + lane, o);
}

__global__ void k_gemm_l2(const float* __restrict__ W) {
    gemm128_body(g_h1, W, g_hp, NN, blockIdx.x);
}

// agg layer-2 fused with linear head; also re-zeroes g_deg/g_stat for the
// next deterministic call.
__global__ void k_agg2_head(const float* __restrict__ bias,
                            const float* __restrict__ Wl,
                            const float* __restrict__ bl,
                            float* __restrict__ out) {
    __shared__ float Wls[C * 10];
    __shared__ float bls[10];
    int tid = threadIdx.x;

    // reset scratch for next call (not read by this kernel)
    {
        int z = blockIdx.x * 8 + (tid & 7);
        if (tid < 8 && z < NN) g_deg[z] = 0;
        if (blockIdx.x == 0 && tid >= 8 && tid < 8 + SCAN_BLOCKS)
            g_stat[tid - 8] = 0ull;
    }

    for (int i = tid; i < C * 10; i += blockDim.x) Wls[i] = Wl[i];
    if (tid < 10) bls[tid] = bl[tid];
    __syncthreads();

    int node = blockIdx.x * (blockDim.x >> 5) + (tid >> 5);
    if (node >= NN) return;
    int lane = tid & 31;

    float4 o = agg_row(g_hp, (const float4*)bias, node, lane);

    float pc[10];
    const float* wr = &Wls[(4 * lane) * 10];
    #pragma unroll
    for (int c = 0; c < 10; c++)
        pc[c] = o.x * wr[c] + o.y * wr[10 + c] + o.z * wr[20 + c] + o.w * wr[30 + c];

    #pragma unroll
    for (int c = 0; c < 10; c++) {
        #pragma unroll
        for (int off = 16; off > 0; off >>= 1)
            pc[c] += __shfl_down_sync(0xffffffffu, pc[c], off);
    }
    if (lane == 0) {
        #pragma unroll
        for (int c = 0; c < 10; c++)
            out[(size_t)node * 10 + c] = pc[c] + bls[c];
    }
}

// ---------------- launch (kernel launches ONLY; 6 launches) ----------------
extern "C" void kernel_launch(void* const* d_in, const int* in_sizes, int n_in,
                              void* d_out, int out_size) {
    const float* x   = (const float*)d_in[0];
    const int*   ei  = (const int*)d_in[1];
    const float* W1  = (const float*)d_in[2];
    const float* b1  = (const float*)d_in[3];
    const float* W2  = (const float*)d_in[4];
    const float* b2  = (const float*)d_in[5];
    const float* Wl  = (const float*)d_in[6];
    const float* bl  = (const float*)d_in[7];
    float* out = (float*)d_out;

    k_count_deg<<<FILL_GRID, 256>>>(ei);             // g_deg pre-zeroed
    k_scan1<<<SCAN_BLOCKS, 1024>>>();                // dinv + rowptr + cnt
    k_gemm1_fill<<<GEMM_GRID + FILL_GRID, 256>>>(x, W1, ei);
    k_agg_l1<<<AGG_GRID, 256>>>(b1);
    k_gemm_l2<<<GEMM_GRID, 256>>>(W2);
    k_agg2_head<<<AGG_GRID, 256>>>(b2, Wl, bl, out);
}

// round 10
// speedup vs baseline: 1.0606x; 1.0606x over previous
#include <cuda_runtime.h>
#include <cuda_fp16.h>
#include <stdint.h>

#define NN 50000
#define EE 800000
#define C  128
#define SCAN_BLOCKS ((NN + 1023) / 1024)   // 49
#define GEMM_GRID   ((NN + 127) / 128)     // 391
#define FILL_GRID   ((EE / 4 + 255) / 256) // 782
#define AGG_GRID    ((NN + 7) / 8)         // 6250

// ---------------- scratch (device globals; no allocation) ----------------
// g_deg / g_stat are zero on entry: zero-initialized at load, re-zeroed by
// k_agg2_head (last kernel of every call). Deterministic across replays.
__device__ __half g_hp[(size_t)NN * C];   // h' (dinv-scaled gemm out, fp16)
__device__ __half g_h1[(size_t)NN * C];   // h1 (post agg/relu, fp16)
__device__ int    g_deg[NN];
__device__ int    g_rowptr[NN + 1];
__device__ int    g_cnt[NN];
__device__ int    g_srcs[EE];
__device__ unsigned long long g_stat[SCAN_BLOCKS];  // (value<<2)|flag

// ---------------- vector load helpers ----------------
__device__ __forceinline__ float4 ld4v(const float* X, size_t off4) {
    return ((const float4*)X)[off4];
}
__device__ __forceinline__ float4 ld4v(const __half* X, size_t off4) {
    uint2 u = ((const uint2*)X)[off4];
    __half2 a = *(__half2*)&u.x, b = *(__half2*)&u.y;
    float2 fa = __half22float2(a), fb = __half22float2(b);
    return make_float4(fa.x, fa.y, fb.x, fb.y);
}
__device__ __forceinline__ void st4h(__half* out, size_t off4, float4 v) {
    uint2 u;
    __half2 lo = __floats2half2_rn(v.x, v.y);
    __half2 hi = __floats2half2_rn(v.z, v.w);
    u.x = *(unsigned*)&lo; u.y = *(unsigned*)&hi;
    ((uint2*)out)[off4] = u;
}

// ---------------- CSR: count ----------------
__global__ void k_count_deg(const int* __restrict__ ei) {
    int e4 = blockIdx.x * blockDim.x + threadIdx.x;
    if (e4 < EE / 4) {
        int4 d = ((const int4*)(ei + EE))[e4];
        atomicAdd(&g_deg[d.x], 1);
        atomicAdd(&g_deg[d.y], 1);
        atomicAdd(&g_deg[d.z], 1);
        atomicAdd(&g_deg[d.w], 1);
    }
}

// ---------------- CSR: single-pass scan (decoupled lookback) -------------
__global__ void k_scan1() {
    __shared__ int wsum[32];
    __shared__ int s_off;
    int tid = threadIdx.x;
    int lane = tid & 31, wid = tid >> 5;
    int bid = blockIdx.x;
    int i = bid * 1024 + tid;
    int v = (i < NN) ? g_deg[i] : 0;

    int s = v;
    #pragma unroll
    for (int off = 1; off < 32; off <<= 1) {
        int t = __shfl_up_sync(0xffffffffu, s, off);
        if (lane >= off) s += t;
    }
    if (lane == 31) wsum[wid] = s;
    __syncthreads();
    if (wid == 0) {
        int ws = wsum[lane];
        #pragma unroll
        for (int off = 1; off < 32; off <<= 1) {
            int t = __shfl_up_sync(0xffffffffu, ws, off);
            if (lane >= off) ws += t;
        }
        wsum[lane] = ws;
    }
    __syncthreads();

    int excl = s - v + (wid > 0 ? wsum[wid - 1] : 0);
    int T = wsum[31];

    if (tid == 0) {
        if (bid == 0) {
            atomicExch(&g_stat[0], ((unsigned long long)T << 2) | 2ull);
            s_off = 0;
        } else {
            atomicExch(&g_stat[bid], ((unsigned long long)T << 2) | 1ull);
            int sum = 0;
            int p = bid - 1;
            while (true) {
                unsigned long long st;
                do { st = atomicAdd(&g_stat[p], 0ull); } while ((st & 3ull) == 0ull);
                sum += (int)(st >> 2);
                if ((st & 3ull) == 2ull) break;
                p--;
            }
            atomicExch(&g_stat[bid], ((unsigned long long)(sum + T) << 2) | 2ull);
            s_off = sum;
        }
    }
    __syncthreads();

    int off = s_off;
    if (i < NN) {
        int rp = excl + off;
        g_rowptr[i] = rp;
        g_cnt[i]    = rp;
    }
    if (bid == SCAN_BLOCKS - 1 && tid == 0)
        g_rowptr[NN] = off + T;
}

// ---------------- FP16 tensor-core GEMM (m16n8k16) -----------------------
__device__ __forceinline__ void mma_fp16(float* c, unsigned a0, unsigned a1,
                                         unsigned a2, unsigned a3,
                                         unsigned b0, unsigned b1) {
    asm volatile(
        "mma.sync.aligned.m16n8k16.row.col.f32.f16.f16.f32 "
        "{%0,%1,%2,%3}, {%4,%5,%6,%7}, {%8,%9}, {%0,%1,%2,%3};"
        : "+f"(c[0]), "+f"(c[1]), "+f"(c[2]), "+f"(c[3])
        : "r"(a0), "r"(a1), "r"(a2), "r"(a3), "r"(b0), "r"(b1));
}

#define KS 72

template <typename Tin>
__device__ __forceinline__ void gemm128_body(const Tin* __restrict__ X,
                                             const float* __restrict__ W,
                                             __half* __restrict__ out,
                                             int n, int bx) {
    __shared__ __half Xs[128 * KS];
    __shared__ __half Wt[128 * KS];

    int tid = threadIdx.x;
    int warp = tid >> 5, lane = tid & 31;
    int warp_m = warp >> 2, warp_n = warp & 3;
    int row0 = bx * 128;
    int lq = lane & 3, lg = lane >> 2;

    float acc[4][4][4];
    #pragma unroll
    for (int mt = 0; mt < 4; mt++)
        #pragma unroll
        for (int nt = 0; nt < 4; nt++)
            #pragma unroll
            for (int k = 0; k < 4; k++) acc[mt][nt][k] = 0.f;

    #pragma unroll
    for (int kc = 0; kc < 2; kc++) {
        #pragma unroll
        for (int i = 0; i < 8; i++) {
            int idx = tid + 256 * i;
            int r = idx >> 4, kq = idx & 15;
            float4 v = make_float4(0.f, 0.f, 0.f, 0.f);
            if (row0 + r < n)
                v = ld4v(X, (size_t)(row0 + r) * 32 + kc * 16 + kq);
            __half2* p = (__half2*)&Xs[r * KS + kq * 4];
            p[0] = __floats2half2_rn(v.x, v.y);
            p[1] = __floats2half2_rn(v.z, v.w);
        }
        #pragma unroll
        for (int i = 0; i < 4; i++) {
            int idx = tid + 256 * i;
            int kp = idx & 31, n4 = idx >> 5;
            int k0 = kc * 64 + kp * 2;
            float4 a = ((const float4*)W)[(size_t)k0 * 32 + n4];
            float4 b = ((const float4*)W)[(size_t)(k0 + 1) * 32 + n4];
            int nb = n4 * 4;
            *(__half2*)&Wt[(nb + 0) * KS + kp * 2] = __floats2half2_rn(a.x, b.x);
            *(__half2*)&Wt[(nb + 1) * KS + kp * 2] = __floats2half2_rn(a.y, b.y);
            *(__half2*)&Wt[(nb + 2) * KS + kp * 2] = __floats2half2_rn(a.z, b.z);
            *(__half2*)&Wt[(nb + 3) * KS + kp * 2] = __floats2half2_rn(a.w, b.w);
        }
        __syncthreads();

        #pragma unroll
        for (int ks = 0; ks < 4; ks++) {
            int kb = ks * 16;
            unsigned b[4][2];
            #pragma unroll
            for (int nt = 0; nt < 4; nt++) {
                int nn = warp_n * 32 + nt * 8 + lg;
                b[nt][0] = *(unsigned*)&Wt[nn * KS + kb + 2 * lq];
                b[nt][1] = *(unsigned*)&Wt[nn * KS + kb + 8 + 2 * lq];
            }
            #pragma unroll
            for (int mt = 0; mt < 4; mt++) {
                int mm = warp_m * 64 + mt * 16 + lg;
                unsigned a0 = *(unsigned*)&Xs[mm * KS + kb + 2 * lq];
                unsigned a1 = *(unsigned*)&Xs[(mm + 8) * KS + kb + 2 * lq];
                unsigned a2 = *(unsigned*)&Xs[mm * KS + kb + 8 + 2 * lq];
                unsigned a3 = *(unsigned*)&Xs[(mm + 8) * KS + kb + 8 + 2 * lq];
                #pragma unroll
                for (int nt = 0; nt < 4; nt++)
                    mma_fp16(acc[mt][nt], a0, a1, a2, a3, b[nt][0], b[nt][1]);
            }
        }
        __syncthreads();
    }

    // epilogue: scale row by rsqrt(deg+1), write fp16
    #pragma unroll
    for (int mt = 0; mt < 4; mt++) {
        int r = row0 + warp_m * 64 + mt * 16 + lg;
        float s0 = (r < n)     ? rsqrtf((float)g_deg[r] + 1.0f)     : 0.f;
        float s1 = (r + 8 < n) ? rsqrtf((float)g_deg[r + 8] + 1.0f) : 0.f;
        #pragma unroll
        for (int nt = 0; nt < 4; nt++) {
            int cc = warp_n * 32 + nt * 8 + lq * 2;
            if (r < n) {
                __half2 h = __floats2half2_rn(acc[mt][nt][0] * s0, acc[mt][nt][1] * s0);
                *(__half2*)&out[(size_t)r * C + cc] = h;
            }
            if (r + 8 < n) {
                __half2 h = __floats2half2_rn(acc[mt][nt][2] * s1, acc[mt][nt][3] * s1);
                *(__half2*)&out[(size_t)(r + 8) * C + cc] = h;
            }
        }
    }
}

// ---------------- fat kernel: GEMM layer1 + fill_csr ----------------
__global__ void k_gemm1_fill(const float* __restrict__ X,
                             const float* __restrict__ W,
                             const int* __restrict__ ei) {
    if (blockIdx.x < GEMM_GRID) {
        gemm128_body(X, W, g_hp, NN, blockIdx.x);
    } else {
        int e4 = (blockIdx.x - GEMM_GRID) * blockDim.x + threadIdx.x;
        if (e4 < EE / 4) {
            int4 s = ((const int4*)ei)[e4];
            int4 d = ((const int4*)(ei + EE))[e4];
            g_srcs[atomicAdd(&g_cnt[d.x], 1)] = s.x;
            g_srcs[atomicAdd(&g_cnt[d.y], 1)] = s.y;
            g_srcs[atomicAdd(&g_cnt[d.z], 1)] = s.z;
            g_srcs[atomicAdd(&g_cnt[d.w], 1)] = s.w;
        }
    }
}

// ---------------- aggregation over pre-normalized fp16 h' -----------------
// 4 independent gathers in flight, 2 accumulators (regs stay low).
__device__ __forceinline__ float4 agg_row(const __half* __restrict__ hp,
                                          const float4* __restrict__ b4,
                                          int node, int lane) {
    float di = rsqrtf((float)g_deg[node] + 1.0f);
    int e = g_rowptr[node], end = g_rowptr[node + 1];

    float4 a0 = make_float4(0.f, 0.f, 0.f, 0.f);
    float4 a1 = make_float4(0.f, 0.f, 0.f, 0.f);
    for (; e + 3 < end; e += 4) {
        int s0 = g_srcs[e],     s1 = g_srcs[e + 1];
        int s2 = g_srcs[e + 2], s3 = g_srcs[e + 3];
        float4 v0 = ld4v(hp, (size_t)s0 * 32 + lane);
        float4 v1 = ld4v(hp, (size_t)s1 * 32 + lane);
        float4 v2 = ld4v(hp, (size_t)s2 * 32 + lane);
        float4 v3 = ld4v(hp, (size_t)s3 * 32 + lane);
        a0.x += v0.x + v2.x; a0.y += v0.y + v2.y;
        a0.z += v0.z + v2.z; a0.w += v0.w + v2.w;
        a1.x += v1.x + v3.x; a1.y += v1.y + v3.y;
        a1.z += v1.z + v3.z; a1.w += v1.w + v3.w;
    }
    for (; e < end; e++) {
        float4 v = ld4v(hp, (size_t)g_srcs[e] * 32 + lane);
        a0.x += v.x; a0.y += v.y; a0.z += v.z; a0.w += v.w;
    }
    float4 sv = ld4v(hp, (size_t)node * 32 + lane);  // self
    a0.x += a1.x + sv.x; a0.y += a1.y + sv.y;
    a0.z += a1.z + sv.z; a0.w += a1.w + sv.w;

    float4 b = b4[lane];
    float4 o;
    o.x = fmaxf(fmaf(di, a0.x, b.x), 0.f);
    o.y = fmaxf(fmaf(di, a0.y, b.y), 0.f);
    o.z = fmaxf(fmaf(di, a0.z, b.z), 0.f);
    o.w = fmaxf(fmaf(di, a0.w, b.w), 0.f);
    return o;
}

__global__ void __launch_bounds__(256, 6)
k_agg_l1(const float* __restrict__ bias) {
    int node = blockIdx.x * (blockDim.x >> 5) + (threadIdx.x >> 5);
    if (node >= NN) return;
    int lane = threadIdx.x & 31;
    float4 o = agg_row(g_hp, (const float4*)bias, node, lane);
    st4h(g_h1, (size_t)node * 32 + lane, o);
}

__global__ void k_gemm_l2(const float* __restrict__ W) {
    gemm128_body(g_h1, W, g_hp, NN, blockIdx.x);
}

// agg layer-2 fused with linear head; also re-zeroes g_deg/g_stat.
__global__ void __launch_bounds__(256, 6)
k_agg2_head(const float* __restrict__ bias,
            const float* __restrict__ Wl,
            const float* __restrict__ bl,
            float* __restrict__ out) {
    __shared__ float Wls[C * 10];
    __shared__ float bls[10];
    int tid = threadIdx.x;

    for (int i = tid; i < C * 10; i += blockDim.x) Wls[i] = Wl[i];
    if (tid < 10) bls[tid] = bl[tid];
    if (blockIdx.x == 0 && tid < SCAN_BLOCKS) g_stat[tid] = 0ull;
    __syncthreads();

    int node = blockIdx.x * (blockDim.x >> 5) + (tid >> 5);
    if (node >= NN) return;
    int lane = tid & 31;

    float4 o = agg_row(g_hp, (const float4*)bias, node, lane);

    // reset deg for next call (after last read of g_deg for this node)
    if (lane == 0) g_deg[node] = 0;

    float pc[10];
    const float* wr = &Wls[(4 * lane) * 10];
    #pragma unroll
    for (int c = 0; c < 10; c++)
        pc[c] = o.x * wr[c] + o.y * wr[10 + c] + o.z * wr[20 + c] + o.w * wr[30 + c];

    #pragma unroll
    for (int c = 0; c < 10; c++) {
        #pragma unroll
        for (int off = 16; off > 0; off >>= 1)
            pc[c] += __shfl_down_sync(0xffffffffu, pc[c], off);
    }
    if (lane == 0) {
        #pragma unroll
        for (int c = 0; c < 10; c++)
            out[(size_t)node * 10 + c] = pc[c] + bls[c];
    }
}

// ---------------- launch (kernel launches ONLY; 6 launches) ----------------
extern "C" void kernel_launch(void* const* d_in, const int* in_sizes, int n_in,
                              void* d_out, int out_size) {
    const float* x   = (const float*)d_in[0];
    const int*   ei  = (const int*)d_in[1];
    const float* W1  = (const float*)d_in[2];
    const float* b1  = (const float*)d_in[3];
    const float* W2  = (const float*)d_in[4];
    const float* b2  = (const float*)d_in[5];
    const float* Wl  = (const float*)d_in[6];
    const float* bl  = (const float*)d_in[7];
    float* out = (float*)d_out;

    k_count_deg<<<FILL_GRID, 256>>>(ei);             // g_deg pre-zeroed
    k_scan1<<<SCAN_BLOCKS, 1024>>>();                // rowptr + cnt
    k_gemm1_fill<<<GEMM_GRID + FILL_GRID, 256>>>(x, W1, ei);
    k_agg_l1<<<AGG_GRID, 256>>>(b1);
    k_gemm_l2<<<GEMM_GRID, 256>>>(W2);
    k_agg2_head<<<AGG_GRID, 256>>>(b2, Wl, bl, out);
}

// round 11
// speedup vs baseline: 1.0743x; 1.0129x over previous
#include <cuda_runtime.h>
#include <cuda_fp16.h>
#include <stdint.h>

#define NN 50000
#define EE 800000
#define C  128
#define SCAN_BLOCKS ((NN + 1023) / 1024)   // 49
#define GEMM_GRID   ((NN + 127) / 128)     // 391
#define FILL_GRID   ((EE / 4 + 255) / 256) // 782
#define AGG_GRID    ((NN + 7) / 8)         // 6250

// ---------------- scratch (device globals; no allocation) ----------------
// g_deg is zero on entry: zero-initialized at load, re-zeroed by k_agg2_head.
// g_bar is a monotonic ticket counter (never reset; replay-safe).
__device__ __half g_hp[(size_t)NN * C];
__device__ __half g_h1[(size_t)NN * C];
__device__ int    g_deg[NN];
__device__ int    g_rowptr[NN + 1];
__device__ int    g_cnt[NN];
__device__ int    g_srcs[EE];
__device__ int    g_bsum[SCAN_BLOCKS];
__device__ unsigned long long g_bar;

// ---------------- vector helpers ----------------
__device__ __forceinline__ float4 ld4v(const float* X, size_t off4) {
    return ((const float4*)X)[off4];
}
__device__ __forceinline__ float4 ld4v(const __half* X, size_t off4) {
    uint2 u = ((const uint2*)X)[off4];
    __half2 a = *(__half2*)&u.x, b = *(__half2*)&u.y;
    float2 fa = __half22float2(a), fb = __half22float2(b);
    return make_float4(fa.x, fa.y, fb.x, fb.y);
}
__device__ __forceinline__ void st4h(__half* out, size_t off4, float4 v) {
    uint2 u;
    __half2 lo = __floats2half2_rn(v.x, v.y);
    __half2 hi = __floats2half2_rn(v.z, v.w);
    u.x = *(unsigned*)&lo; u.y = *(unsigned*)&hi;
    ((uint2*)out)[off4] = u;
}

// ---------------- CSR: count ----------------
__global__ void k_count_deg(const int* __restrict__ ei) {
    int e4 = blockIdx.x * blockDim.x + threadIdx.x;
    if (e4 < EE / 4) {
        int4 d = ((const int4*)(ei + EE))[e4];
        atomicAdd(&g_deg[d.x], 1);
        atomicAdd(&g_deg[d.y], 1);
        atomicAdd(&g_deg[d.z], 1);
        atomicAdd(&g_deg[d.w], 1);
    }
}

// ---------------- CSR: single-launch scan with grid barrier --------------
// 49 blocks x 1024 thr, all co-resident (49 <= 148 SMs) -> spin is safe.
__global__ void k_scan1() {
    __shared__ int wsum[32];
    __shared__ int sb[SCAN_BLOCKS];
    __shared__ int s_off;
    int tid = threadIdx.x;
    int lane = tid & 31, wid = tid >> 5;
    int bid = blockIdx.x;
    int i = bid * 1024 + tid;
    int v = (i < NN) ? g_deg[i] : 0;

    int s = v;
    #pragma unroll
    for (int off = 1; off < 32; off <<= 1) {
        int t = __shfl_up_sync(0xffffffffu, s, off);
        if (lane >= off) s += t;
    }
    if (lane == 31) wsum[wid] = s;
    __syncthreads();
    if (wid == 0) {
        int ws = wsum[lane];
        #pragma unroll
        for (int off = 1; off < 32; off <<= 1) {
            int t = __shfl_up_sync(0xffffffffu, ws, off);
            if (lane >= off) ws += t;
        }
        wsum[lane] = ws;
    }
    __syncthreads();

    int excl = s - v + (wid > 0 ? wsum[wid - 1] : 0);
    int T = wsum[31];

    // publish block total, then grid barrier (monotonic ticket; replay-safe)
    if (tid == 0) {
        g_bsum[bid] = T;
        __threadfence();
        unsigned long long ticket = atomicAdd(&g_bar, 1ull);
        unsigned long long target =
            (ticket / (unsigned long long)SCAN_BLOCKS + 1ull) *
            (unsigned long long)SCAN_BLOCKS;
        while (*((volatile unsigned long long*)&g_bar) < target) { }
        __threadfence();
    }
    __syncthreads();

    if (tid < SCAN_BLOCKS) sb[tid] = g_bsum[tid];
    __syncthreads();
    if (tid == 0) {
        int sum = 0;
        for (int j = 0; j < bid; j++) sum += sb[j];
        s_off = sum;
    }
    __syncthreads();

    int off = s_off;
    if (i < NN) {
        int rp = excl + off;
        g_rowptr[i] = rp;
        g_cnt[i]    = rp;
    }
    if (bid == SCAN_BLOCKS - 1 && tid == 0)
        g_rowptr[NN] = off + T;
}

// ---------------- FP16 tensor-core GEMM (m16n8k16) -----------------------
__device__ __forceinline__ void mma_fp16(float* c, unsigned a0, unsigned a1,
                                         unsigned a2, unsigned a3,
                                         unsigned b0, unsigned b1) {
    asm volatile(
        "mma.sync.aligned.m16n8k16.row.col.f32.f16.f16.f32 "
        "{%0,%1,%2,%3}, {%4,%5,%6,%7}, {%8,%9}, {%0,%1,%2,%3};"
        : "+f"(c[0]), "+f"(c[1]), "+f"(c[2]), "+f"(c[3])
        : "r"(a0), "r"(a1), "r"(a2), "r"(a3), "r"(b0), "r"(b1));
}

#define KS 72

template <typename Tin>
__device__ __forceinline__ void gemm128_body(const Tin* __restrict__ X,
                                             const float* __restrict__ W,
                                             __half* __restrict__ out,
                                             int n, int bx) {
    __shared__ __half Xs[128 * KS];
    __shared__ __half Wt[128 * KS];

    int tid = threadIdx.x;
    int warp = tid >> 5, lane = tid & 31;
    int warp_m = warp >> 2, warp_n = warp & 3;
    int row0 = bx * 128;
    int lq = lane & 3, lg = lane >> 2;

    float acc[4][4][4];
    #pragma unroll
    for (int mt = 0; mt < 4; mt++)
        #pragma unroll
        for (int nt = 0; nt < 4; nt++)
            #pragma unroll
            for (int k = 0; k < 4; k++) acc[mt][nt][k] = 0.f;

    #pragma unroll
    for (int kc = 0; kc < 2; kc++) {
        #pragma unroll
        for (int i = 0; i < 8; i++) {
            int idx = tid + 256 * i;
            int r = idx >> 4, kq = idx & 15;
            float4 v = make_float4(0.f, 0.f, 0.f, 0.f);
            if (row0 + r < n)
                v = ld4v(X, (size_t)(row0 + r) * 32 + kc * 16 + kq);
            __half2* p = (__half2*)&Xs[r * KS + kq * 4];
            p[0] = __floats2half2_rn(v.x, v.y);
            p[1] = __floats2half2_rn(v.z, v.w);
        }
        #pragma unroll
        for (int i = 0; i < 4; i++) {
            int idx = tid + 256 * i;
            int kp = idx & 31, n4 = idx >> 5;
            int k0 = kc * 64 + kp * 2;
            float4 a = ((const float4*)W)[(size_t)k0 * 32 + n4];
            float4 b = ((const float4*)W)[(size_t)(k0 + 1) * 32 + n4];
            int nb = n4 * 4;
            *(__half2*)&Wt[(nb + 0) * KS + kp * 2] = __floats2half2_rn(a.x, b.x);
            *(__half2*)&Wt[(nb + 1) * KS + kp * 2] = __floats2half2_rn(a.y, b.y);
            *(__half2*)&Wt[(nb + 2) * KS + kp * 2] = __floats2half2_rn(a.z, b.z);
            *(__half2*)&Wt[(nb + 3) * KS + kp * 2] = __floats2half2_rn(a.w, b.w);
        }
        __syncthreads();

        #pragma unroll
        for (int ks = 0; ks < 4; ks++) {
            int kb = ks * 16;
            unsigned b[4][2];
            #pragma unroll
            for (int nt = 0; nt < 4; nt++) {
                int nn = warp_n * 32 + nt * 8 + lg;
                b[nt][0] = *(unsigned*)&Wt[nn * KS + kb + 2 * lq];
                b[nt][1] = *(unsigned*)&Wt[nn * KS + kb + 8 + 2 * lq];
            }
            #pragma unroll
            for (int mt = 0; mt < 4; mt++) {
                int mm = warp_m * 64 + mt * 16 + lg;
                unsigned a0 = *(unsigned*)&Xs[mm * KS + kb + 2 * lq];
                unsigned a1 = *(unsigned*)&Xs[(mm + 8) * KS + kb + 2 * lq];
                unsigned a2 = *(unsigned*)&Xs[mm * KS + kb + 8 + 2 * lq];
                unsigned a3 = *(unsigned*)&Xs[(mm + 8) * KS + kb + 8 + 2 * lq];
                #pragma unroll
                for (int nt = 0; nt < 4; nt++)
                    mma_fp16(acc[mt][nt], a0, a1, a2, a3, b[nt][0], b[nt][1]);
            }
        }
        __syncthreads();
    }

    #pragma unroll
    for (int mt = 0; mt < 4; mt++) {
        int r = row0 + warp_m * 64 + mt * 16 + lg;
        float s0 = (r < n)     ? rsqrtf((float)g_deg[r] + 1.0f)     : 0.f;
        float s1 = (r + 8 < n) ? rsqrtf((float)g_deg[r + 8] + 1.0f) : 0.f;
        #pragma unroll
        for (int nt = 0; nt < 4; nt++) {
            int cc = warp_n * 32 + nt * 8 + lq * 2;
            if (r < n) {
                __half2 h = __floats2half2_rn(acc[mt][nt][0] * s0, acc[mt][nt][1] * s0);
                *(__half2*)&out[(size_t)r * C + cc] = h;
            }
            if (r + 8 < n) {
                __half2 h = __floats2half2_rn(acc[mt][nt][2] * s1, acc[mt][nt][3] * s1);
                *(__half2*)&out[(size_t)(r + 8) * C + cc] = h;
            }
        }
    }
}

// ---------------- fat kernel: GEMM layer1 + fill_csr ----------------
__global__ void k_gemm1_fill(const float* __restrict__ X,
                             const float* __restrict__ W,
                             const int* __restrict__ ei) {
    if (blockIdx.x < GEMM_GRID) {
        gemm128_body(X, W, g_hp, NN, blockIdx.x);
    } else {
        int e4 = (blockIdx.x - GEMM_GRID) * blockDim.x + threadIdx.x;
        if (e4 < EE / 4) {
            int4 s = ((const int4*)ei)[e4];
            int4 d = ((const int4*)(ei + EE))[e4];
            g_srcs[atomicAdd(&g_cnt[d.x], 1)] = s.x;
            g_srcs[atomicAdd(&g_cnt[d.y], 1)] = s.y;
            g_srcs[atomicAdd(&g_cnt[d.z], 1)] = s.z;
            g_srcs[atomicAdd(&g_cnt[d.w], 1)] = s.w;
        }
    }
}

// ---------------- aggregation: HADD2 accumulate, flush to fp32 every 8 ----
__device__ __forceinline__ float4 agg_row(const __half* __restrict__ hp,
                                          const float4* __restrict__ b4,
                                          int node, int lane) {
    float di = rsqrtf((float)g_deg[node] + 1.0f);
    int e = g_rowptr[node], end = g_rowptr[node + 1];
    const uint2* hp2 = (const uint2*)hp;

    float ax = 0.f, ay = 0.f, az = 0.f, aw = 0.f;
    __half2 z = __floats2half2_rn(0.f, 0.f);
    __half2 A = z, B = z, Cc = z, D = z;   // A/B: stream0 feats 01/23, Cc/D: stream1
    int since = 0;

    for (; e + 3 < end; e += 4) {
        int s0 = g_srcs[e],     s1 = g_srcs[e + 1];
        int s2 = g_srcs[e + 2], s3 = g_srcs[e + 3];
        uint2 u0 = hp2[(size_t)s0 * 32 + lane];
        uint2 u1 = hp2[(size_t)s1 * 32 + lane];
        uint2 u2 = hp2[(size_t)s2 * 32 + lane];
        uint2 u3 = hp2[(size_t)s3 * 32 + lane];
        A  = __hadd2(A,  *(__half2*)&u0.x);  B  = __hadd2(B,  *(__half2*)&u0.y);
        Cc = __hadd2(Cc, *(__half2*)&u1.x);  D  = __hadd2(D,  *(__half2*)&u1.y);
        A  = __hadd2(A,  *(__half2*)&u2.x);  B  = __hadd2(B,  *(__half2*)&u2.y);
        Cc = __hadd2(Cc, *(__half2*)&u3.x);  D  = __hadd2(D,  *(__half2*)&u3.y);
        since += 4;
        if (since == 8) {   // each fp16 acc holds <=4 values per window
            float2 fa = __half22float2(A),  fb = __half22float2(B);
            float2 fc = __half22float2(Cc), fd = __half22float2(D);
            ax += fa.x + fc.x; ay += fa.y + fc.y;
            az += fb.x + fd.x; aw += fb.y + fd.y;
            A = B = Cc = D = z; since = 0;
        }
    }
    for (; e < end; e++) {
        uint2 u = hp2[(size_t)g_srcs[e] * 32 + lane];
        A = __hadd2(A, *(__half2*)&u.x);  B = __hadd2(B, *(__half2*)&u.y);
    }
    // self
    {
        uint2 u = hp2[(size_t)node * 32 + lane];
        Cc = __hadd2(Cc, *(__half2*)&u.x);  D = __hadd2(D, *(__half2*)&u.y);
    }
    {
        float2 fa = __half22float2(A),  fb = __half22float2(B);
        float2 fc = __half22float2(Cc), fd = __half22float2(D);
        ax += fa.x + fc.x; ay += fa.y + fc.y;
        az += fb.x + fd.x; aw += fb.y + fd.y;
    }

    float4 b = b4[lane];
    float4 o;
    o.x = fmaxf(fmaf(di, ax, b.x), 0.f);
    o.y = fmaxf(fmaf(di, ay, b.y), 0.f);
    o.z = fmaxf(fmaf(di, az, b.z), 0.f);
    o.w = fmaxf(fmaf(di, aw, b.w), 0.f);
    return o;
}

__global__ void __launch_bounds__(256, 6)
k_agg_l1(const float* __restrict__ bias) {
    int node = blockIdx.x * (blockDim.x >> 5) + (threadIdx.x >> 5);
    if (node >= NN) return;
    int lane = threadIdx.x & 31;
    float4 o = agg_row(g_hp, (const float4*)bias, node, lane);
    st4h(g_h1, (size_t)node * 32 + lane, o);
}

__global__ void k_gemm_l2(const float* __restrict__ W) {
    gemm128_body(g_h1, W, g_hp, NN, blockIdx.x);
}

// agg layer-2 fused with linear head; re-zeroes g_deg for next call.
__global__ void __launch_bounds__(256, 6)
k_agg2_head(const float* __restrict__ bias,
            const float* __restrict__ Wl,
            const float* __restrict__ bl,
            float* __restrict__ out) {
    __shared__ float Wls[C * 10];
    __shared__ float bls[10];
    int tid = threadIdx.x;

    for (int i = tid; i < C * 10; i += blockDim.x) Wls[i] = Wl[i];
    if (tid < 10) bls[tid] = bl[tid];
    __syncthreads();

    int node = blockIdx.x * (blockDim.x >> 5) + (tid >> 5);
    if (node >= NN) return;
    int lane = tid & 31;

    float4 o = agg_row(g_hp, (const float4*)bias, node, lane);

    if (lane == 0) g_deg[node] = 0;   // reset for next call (after last read)

    float pc[10];
    const float* wr = &Wls[(4 * lane) * 10];
    #pragma unroll
    for (int c = 0; c < 10; c++)
        pc[c] = o.x * wr[c] + o.y * wr[10 + c] + o.z * wr[20 + c] + o.w * wr[30 + c];

    #pragma unroll
    for (int c = 0; c < 10; c++) {
        #pragma unroll
        for (int off = 16; off > 0; off >>= 1)
            pc[c] += __shfl_down_sync(0xffffffffu, pc[c], off);
    }
    if (lane == 0) {
        #pragma unroll
        for (int c = 0; c < 10; c++)
            out[(size_t)node * 10 + c] = pc[c] + bls[c];
    }
}

// ---------------- launch (kernel launches ONLY; 6 launches) ----------------
extern "C" void kernel_launch(void* const* d_in, const int* in_sizes, int n_in,
                              void* d_out, int out_size) {
    const float* x   = (const float*)d_in[0];
    const int*   ei  = (const int*)d_in[1];
    const float* W1  = (const float*)d_in[2];
    const float* b1  = (const float*)d_in[3];
    const float* W2  = (const float*)d_in[4];
    const float* b2  = (const float*)d_in[5];
    const float* Wl  = (const float*)d_in[6];
    const float* bl  = (const float*)d_in[7];
    float* out = (float*)d_out;

    k_count_deg<<<FILL_GRID, 256>>>(ei);
    k_scan1<<<SCAN_BLOCKS, 1024>>>();
    k_gemm1_fill<<<GEMM_GRID + FILL_GRID, 256>>>(x, W1, ei);
    k_agg_l1<<<AGG_GRID, 256>>>(b1);
    k_gemm_l2<<<GEMM_GRID, 256>>>(W2);
    k_agg2_head<<<AGG_GRID, 256>>>(b2, Wl, bl, out);
}